// round 4
// baseline (speedup 1.0000x reference)
#include <cuda_runtime.h>
#include <cstdint>

// InstantNGP multiresolution hash-grid embedding, 3 kernels:
//  1) repack:   linear-level tables (lvl 0-7) -> voxel-contiguous 64B records
//  2) lin:      levels 0-7, 4 lanes per (point,level), one LDG.128 each
//               -> 1 L1 wavefront per (point,level) instead of 8
//  3) hash:     levels 8-15, 1 thread per (point,level), 8 independent gathers
//
// x:      [B, 3]  float32 in [-1, 1)
// tables: [16, 2^19, 2] float32
// out:    [B, 32] float32

#define TSIZE (1u << 19)
#define TMASK (TSIZE - 1u)

__constant__ int c_res_lin[8]  = {16, 20, 25, 32, 40, 50, 64, 80};
__constant__ int c_res_hash[8] = {101, 128, 161, 203, 256, 322, 406, 512};
// cumulative voxel counts (res^3) for linear levels
__constant__ int c_voxoff[9] = {0, 4096, 12096, 27721, 60489,
                                124489, 249489, 511633, 1023633};
#define NVOX_TOTAL 1023633

// 1,023,633 voxels * 64B = 65.5 MB scratch. Static __device__ global: the
// sanctioned scratch mechanism (no dynamic allocation anywhere).
__device__ float4 g_scratch[4 * NVOX_TOTAL];

// ---------------------------------------------------------------------------
// Repack: per voxel u (dense id = i0 + res*i1 + res^2*i2), gather 8 corners
// into a contiguous 64B record. Reads are x-adjacent -> mostly coalesced.
// Record float4 l holds corner pair (x=0, x=1) for (y = l&1, z = l>>1).
// Max table index touched: res^3 + res^2 + res = 518480 < 2^19 (in bounds;
// identical to the reference's own linear-index reach).
// ---------------------------------------------------------------------------
__global__ __launch_bounds__(256) void repack_kernel(const float* __restrict__ tables)
{
    int v = blockIdx.x * 256 + threadIdx.x;
    if (v >= NVOX_TOTAL) return;

    int lvl = 0;
#pragma unroll
    for (int l = 1; l < 8; l++)
        if (v >= c_voxoff[l]) lvl = l;
    int u = v - c_voxoff[lvl];
    int res = c_res_lin[lvl];
    int r2 = res * res;

    const float2* __restrict__ T =
        reinterpret_cast<const float2*>(tables) + (size_t)lvl * TSIZE;

    float2 a0 = __ldg(T + u);            float2 a1 = __ldg(T + u + 1);
    float2 b0 = __ldg(T + u + res);      float2 b1 = __ldg(T + u + res + 1);
    float2 d0 = __ldg(T + u + r2);       float2 d1 = __ldg(T + u + r2 + 1);
    float2 e0 = __ldg(T + u + r2 + res); float2 e1 = __ldg(T + u + r2 + res + 1);

    float4* __restrict__ rec = g_scratch + ((size_t)v << 2);
    rec[0] = make_float4(a0.x, a0.y, a1.x, a1.y);
    rec[1] = make_float4(b0.x, b0.y, b1.x, b1.y);
    rec[2] = make_float4(d0.x, d0.y, d1.x, d1.y);
    rec[3] = make_float4(e0.x, e0.y, e1.x, e1.y);
}

// ---------------------------------------------------------------------------
// Linear levels 0-7: 4 lanes per (point,level). One warp = 1 point x 8 levels.
// Lane l loads float4 l of the voxel record and applies trilerp weights;
// quad-reduce via shuffles; lane 0 stores.
// ---------------------------------------------------------------------------
__global__ __launch_bounds__(256) void lin_kernel(
    const float* __restrict__ x,
    float* __restrict__ out,
    int B)
{
    int t = blockIdx.x * 256 + threadIdx.x;
    int quad = t >> 2;
    int lane = t & 3;
    int p = quad >> 3;
    if (p >= B) return;
    int lvl = quad & 7;

    int res = c_res_lin[lvl];
    int r2 = res * res;
    // Match reference rounding exactly: two IEEE f32 divisions.
    float cell = __fdiv_rn(2.0f, (float)res);

    float x0 = __ldg(x + 3 * p + 0);
    float x1 = __ldg(x + 3 * p + 1);
    float x2 = __ldg(x + 3 * p + 2);

    float p0 = __fdiv_rn(x0 + 1.0f, cell);
    float p1 = __fdiv_rn(x1 + 1.0f, cell);
    float p2 = __fdiv_rn(x2 + 1.0f, cell);

    int i0 = (int)floorf(p0); i0 = min(max(i0, 0), res - 1);
    int i1 = (int)floorf(p1); i1 = min(max(i1, 0), res - 1);
    int i2 = (int)floorf(p2); i2 = min(max(i2, 0), res - 1);

    float w0 = p0 - (float)i0;
    float w1 = p1 - (float)i1;
    float w2 = p2 - (float)i2;
    float u0 = 1.0f - w0, u1 = 1.0f - w1, u2 = 1.0f - w2;

    int u = i0 + res * i1 + r2 * i2;       // dense voxel id within level

    const float4* __restrict__ rec =
        g_scratch + ((size_t)(c_voxoff[lvl] + u) << 2);
    float4 q = __ldg(rec + lane);

    // lane l: q.(x,y) is corner x-bit 0 (weight u0), q.(z,w) is x-bit 1 (w0);
    // y-bit = lane&1, z-bit = lane>>1.
    float wa = ((lane & 1) ? w1 : u1) * ((lane & 2) ? w2 : u2);
    float s0 = wa * (u0 * q.x + w0 * q.z);
    float s1 = wa * (u0 * q.y + w0 * q.w);

    s0 += __shfl_xor_sync(0xFFFFFFFFu, s0, 1);
    s0 += __shfl_xor_sync(0xFFFFFFFFu, s0, 2);
    s1 += __shfl_xor_sync(0xFFFFFFFFu, s1, 1);
    s1 += __shfl_xor_sync(0xFFFFFFFFu, s1, 2);

    if (lane == 0)
        reinterpret_cast<float2*>(out)[(size_t)p * 16 + lvl] = make_float2(s0, s1);
}

// ---------------------------------------------------------------------------
// Hash levels 8-15: 1 thread per (point,level), 8 independent gathers (MLP=8).
// ---------------------------------------------------------------------------
__global__ __launch_bounds__(256) void hash_kernel(
    const float* __restrict__ x,
    const float* __restrict__ tables,
    float* __restrict__ out,
    int B)
{
    int t = blockIdx.x * 256 + threadIdx.x;
    int p = t >> 3;
    if (p >= B) return;
    int h = t & 7;
    int lvl = 8 + h;

    int res = c_res_hash[h];
    float cell = __fdiv_rn(2.0f, (float)res);

    float x0 = __ldg(x + 3 * p + 0);
    float x1 = __ldg(x + 3 * p + 1);
    float x2 = __ldg(x + 3 * p + 2);

    float p0 = __fdiv_rn(x0 + 1.0f, cell);
    float p1 = __fdiv_rn(x1 + 1.0f, cell);
    float p2 = __fdiv_rn(x2 + 1.0f, cell);

    int i0 = (int)floorf(p0); i0 = min(max(i0, 0), res - 1);
    int i1 = (int)floorf(p1); i1 = min(max(i1, 0), res - 1);
    int i2 = (int)floorf(p2); i2 = min(max(i2, 0), res - 1);

    float w0 = p0 - (float)i0;
    float w1 = p1 - (float)i1;
    float w2 = p2 - (float)i2;

    // Spatial hash: h = (x*1) ^ (y*2654435761) ^ (z*805459861), uint32 wrap.
    unsigned a0 = (unsigned)i0;
    unsigned a1 = a0 + 1u;
    unsigned b0 = (unsigned)i1 * 2654435761u;
    unsigned b1 = b0 + 2654435761u;
    unsigned d0 = (unsigned)i2 * 805459861u;
    unsigned d1 = d0 + 805459861u;

    unsigned idx[8];
    idx[0] = (a0 ^ b0 ^ d0) & TMASK;
    idx[1] = (a0 ^ b0 ^ d1) & TMASK;
    idx[2] = (a0 ^ b1 ^ d0) & TMASK;
    idx[3] = (a0 ^ b1 ^ d1) & TMASK;
    idx[4] = (a1 ^ b0 ^ d0) & TMASK;
    idx[5] = (a1 ^ b0 ^ d1) & TMASK;
    idx[6] = (a1 ^ b1 ^ d0) & TMASK;
    idx[7] = (a1 ^ b1 ^ d1) & TMASK;

    const float2* __restrict__ tab =
        reinterpret_cast<const float2*>(tables) + (size_t)lvl * TSIZE;

    float2 v[8];
#pragma unroll
    for (int c = 0; c < 8; c++) v[c] = __ldg(tab + idx[c]);

    float u0 = 1.0f - w0, u1 = 1.0f - w1, u2 = 1.0f - w2;
    float wt[8];
    wt[0] = u0 * u1 * u2;
    wt[1] = u0 * u1 * w2;
    wt[2] = u0 * w1 * u2;
    wt[3] = u0 * w1 * w2;
    wt[4] = w0 * u1 * u2;
    wt[5] = w0 * u1 * w2;
    wt[6] = w0 * w1 * u2;
    wt[7] = w0 * w1 * w2;

    float s0 = 0.0f, s1 = 0.0f;
#pragma unroll
    for (int c = 0; c < 8; c++) {
        s0 += wt[c] * v[c].x;
        s1 += wt[c] * v[c].y;
    }

    reinterpret_cast<float2*>(out)[(size_t)p * 16 + lvl] = make_float2(s0, s1);
}

extern "C" void kernel_launch(void* const* d_in, const int* in_sizes, int n_in,
                              void* d_out, int out_size) {
    const float* x = (const float*)d_in[0];       // [B, 3]
    const float* tables = (const float*)d_in[1];  // [16, 2^19, 2]
    float* out = (float*)d_out;                   // [B, 32]
    int B = in_sizes[0] / 3;

    repack_kernel<<<(NVOX_TOTAL + 255) / 256, 256>>>(tables);

    int lin_threads = B * 32;                     // 8 levels * 4 lanes
    lin_kernel<<<(lin_threads + 255) / 256, 256>>>(x, out, B);

    int hash_threads = B * 8;
    hash_kernel<<<(hash_threads + 255) / 256, 256>>>(x, tables, out, B);
}